// round 14
// baseline (speedup 1.0000x reference)
#include <cuda_runtime.h>

#define VTH 0.5f
#define TAU 0.2f

__device__ __forceinline__ float4 lif4(float4 v) {
    float u = v.x;
    float s0 = (u > VTH) ? 1.0f : 0.0f;
    u = TAU * u * (1.0f - s0) + v.y;
    float s1 = (u > VTH) ? 1.0f : 0.0f;
    u = TAU * u * (1.0f - s1) + v.z;
    float s2 = (u > VTH) ? 1.0f : 0.0f;
    u = TAU * u * (1.0f - s2) + v.w;
    float s3 = (u > VTH) ? 1.0f : 0.0f;
    return make_float4(s0, s1, s2, s3);
}

// Best measured shape: float4 accesses, 4 front-batched independent loads per
// thread (MLP_p1=4), .cs streaming both directions, 256-thread CTAs.
// Guard-free variant: host guarantees n4 % (blockDim.x*4) == 0.
__global__ void __launch_bounds__(256) lif_kernel4_exact(const float4* __restrict__ x,
                                                         float4* __restrict__ out) {
    int base = blockIdx.x * (blockDim.x * 4) + threadIdx.x;
    int i0 = base;
    int i1 = base + blockDim.x;
    int i2 = base + 2 * blockDim.x;
    int i3 = base + 3 * blockDim.x;

    float4 v0 = __ldcs(&x[i0]);
    float4 v1 = __ldcs(&x[i1]);
    float4 v2 = __ldcs(&x[i2]);
    float4 v3 = __ldcs(&x[i3]);
    float4 r0 = lif4(v0);
    float4 r1 = lif4(v1);
    float4 r2 = lif4(v2);
    float4 r3 = lif4(v3);
    __stcs(&out[i0], r0);
    __stcs(&out[i1], r1);
    __stcs(&out[i2], r2);
    __stcs(&out[i3], r3);
}

// Guarded fallback for non-divisible sizes.
__global__ void __launch_bounds__(256) lif_kernel4_guard(const float4* __restrict__ x,
                                                         float4* __restrict__ out,
                                                         int n4) {
    int base = blockIdx.x * (blockDim.x * 4) + threadIdx.x;
#pragma unroll
    for (int j = 0; j < 4; j++) {
        int i = base + j * blockDim.x;
        if (i < n4) __stcs(&out[i], lif4(__ldcs(&x[i])));
    }
}

extern "C" void kernel_launch(void* const* d_in, const int* in_sizes, int n_in,
                              void* d_out, int out_size) {
    const float4* x = (const float4*)d_in[0];
    float4* out = (float4*)d_out;
    int n4 = out_size / 4;  // neurons (4 contiguous f32 steps each)

    int threads = 256;
    int per_block = threads * 4;

    if (n4 % per_block == 0) {
        lif_kernel4_exact<<<n4 / per_block, threads>>>(x, out);
    } else {
        int blocks = (n4 + per_block - 1) / per_block;
        lif_kernel4_guard<<<blocks, threads>>>(x, out, n4);
    }
}

// round 15
// speedup vs baseline: 1.0168x; 1.0168x over previous
#include <cuda_runtime.h>

#define VTH 0.5f
#define TAU 0.2f

__device__ __forceinline__ float4 lif4(float4 v) {
    float u = v.x;
    float s0 = (u > VTH) ? 1.0f : 0.0f;
    u = TAU * u * (1.0f - s0) + v.y;
    float s1 = (u > VTH) ? 1.0f : 0.0f;
    u = TAU * u * (1.0f - s1) + v.z;
    float s2 = (u > VTH) ? 1.0f : 0.0f;
    u = TAU * u * (1.0f - s2) + v.w;
    float s3 = (u > VTH) ? 1.0f : 0.0f;
    return make_float4(s0, s1, s2, s3);
}

// x: [N, 4] f32, steps innermost. Best measured configuration (R4):
// float4 (16B) accesses, 4 front-batched independent loads per thread
// (MLP_p1=4), .cs streaming cache policy on loads and stores, 256-thread CTAs.
// Measured: 35.46us kernel, ~6.0 TB/s (75% of HBM spec) — platform floor for
// a 1:1 read/write stream of 256 MB.
__global__ void __launch_bounds__(256) lif_kernel4(const float4* __restrict__ x,
                                                   float4* __restrict__ out,
                                                   int n4) {
    int base = blockIdx.x * (blockDim.x * 4) + threadIdx.x;
    int i0 = base;
    int i1 = base + blockDim.x;
    int i2 = base + 2 * blockDim.x;
    int i3 = base + 3 * blockDim.x;

    if (i3 < n4) {
        // Fast path (uniform within block): 4 independent loads back-to-back.
        float4 v0 = __ldcs(&x[i0]);
        float4 v1 = __ldcs(&x[i1]);
        float4 v2 = __ldcs(&x[i2]);
        float4 v3 = __ldcs(&x[i3]);
        float4 r0 = lif4(v0);
        float4 r1 = lif4(v1);
        float4 r2 = lif4(v2);
        float4 r3 = lif4(v3);
        __stcs(&out[i0], r0);
        __stcs(&out[i1], r1);
        __stcs(&out[i2], r2);
        __stcs(&out[i3], r3);
    } else {
        if (i0 < n4) __stcs(&out[i0], lif4(__ldcs(&x[i0])));
        if (i1 < n4) __stcs(&out[i1], lif4(__ldcs(&x[i1])));
        if (i2 < n4) __stcs(&out[i2], lif4(__ldcs(&x[i2])));
    }
}

extern "C" void kernel_launch(void* const* d_in, const int* in_sizes, int n_in,
                              void* d_out, int out_size) {
    const float4* x = (const float4*)d_in[0];
    float4* out = (float4*)d_out;
    int n4 = out_size / 4;  // neurons (4 contiguous f32 steps each)

    int threads = 256;
    int per_block = threads * 4;
    int blocks = (n4 + per_block - 1) / per_block;
    lif_kernel4<<<blocks, threads>>>(x, out, n4);
}

// round 17
// speedup vs baseline: 1.0243x; 1.0074x over previous
#include <cuda_runtime.h>

#define VTH 0.5f
#define TAU 0.2f

__device__ __forceinline__ float4 lif4(float4 v) {
    float u = v.x;
    float s0 = (u > VTH) ? 1.0f : 0.0f;
    u = TAU * u * (1.0f - s0) + v.y;
    float s1 = (u > VTH) ? 1.0f : 0.0f;
    u = TAU * u * (1.0f - s1) + v.z;
    float s2 = (u > VTH) ? 1.0f : 0.0f;
    u = TAU * u * (1.0f - s2) + v.w;
    float s3 = (u > VTH) ? 1.0f : 0.0f;
    return make_float4(s0, s1, s2, s3);
}

// FINAL: best measured configuration across 15 rounds of search.
// x: [N, 4] f32, steps innermost. float4 (16B) accesses; 4 front-batched
// independent loads per thread (MLP_p1=4); .cs streaming cache policy on both
// loads and stores; 256-thread CTAs, grid 8192.
//
// Measured floor: ~35.5-36us kernel at ~5.9-6.0 TB/s (~75% of HBM3e spec) —
// the read/write-turnaround ceiling for a mandatory 256 MB 1:1 R/W stream.
// Bounded-out alternatives: 256-bit LDG (L1tex wavefront splits, -9%),
// MLP=8 (cross-CTA L1tex queue spread, -5%), L2 evict_last pinning of input
// or output (neutral without a carveout, which the harness forbids),
// 512-thread CTAs (occupancy loss), guard elimination (noise).
__global__ void __launch_bounds__(256) lif_kernel4(const float4* __restrict__ x,
                                                   float4* __restrict__ out,
                                                   int n4) {
    int base = blockIdx.x * (blockDim.x * 4) + threadIdx.x;
    int i0 = base;
    int i1 = base + blockDim.x;
    int i2 = base + 2 * blockDim.x;
    int i3 = base + 3 * blockDim.x;

    if (i3 < n4) {
        // Fast path (uniform within block): 4 independent loads back-to-back.
        float4 v0 = __ldcs(&x[i0]);
        float4 v1 = __ldcs(&x[i1]);
        float4 v2 = __ldcs(&x[i2]);
        float4 v3 = __ldcs(&x[i3]);
        float4 r0 = lif4(v0);
        float4 r1 = lif4(v1);
        float4 r2 = lif4(v2);
        float4 r3 = lif4(v3);
        __stcs(&out[i0], r0);
        __stcs(&out[i1], r1);
        __stcs(&out[i2], r2);
        __stcs(&out[i3], r3);
    } else {
        if (i0 < n4) __stcs(&out[i0], lif4(__ldcs(&x[i0])));
        if (i1 < n4) __stcs(&out[i1], lif4(__ldcs(&x[i1])));
        if (i2 < n4) __stcs(&out[i2], lif4(__ldcs(&x[i2])));
    }
}

extern "C" void kernel_launch(void* const* d_in, const int* in_sizes, int n_in,
                              void* d_out, int out_size) {
    const float4* x = (const float4*)d_in[0];
    float4* out = (float4*)d_out;
    int n4 = out_size / 4;  // neurons (4 contiguous f32 steps each)

    int threads = 256;
    int per_block = threads * 4;
    int blocks = (n4 + per_block - 1) / per_block;
    lif_kernel4<<<blocks, threads>>>(x, out, n4);
}